// round 2
// baseline (speedup 1.0000x reference)
#include <cuda_runtime.h>

#define NN 50000
#define IC 512
#define OC 128
#define NE 1600000

// Scratch (static __device__ — no allocation in kernel_launch)
__device__ int   g_deg[NN];
__device__ float g_dis[NN];
__device__ float g_y[(size_t)NN * OC];    // (x @ W_enc) * dis[row]
__device__ float g_agg[(size_t)NN * OC];  // sum of y[src] per dst

// ---------------------------------------------------------------------------
// K0: zero deg + agg
__global__ void k_zero() {
    int i = blockIdx.x * blockDim.x + threadIdx.x;
    if (i < NN) g_deg[i] = 0;
    const int tot4 = NN * OC / 4;
    float4* a4 = (float4*)g_agg;
    for (int j = i; j < tot4; j += gridDim.x * blockDim.x)
        a4[j] = make_float4(0.f, 0.f, 0.f, 0.f);
}

// K1: dst-degree histogram (edge_index delivered as int32 by the harness)
__global__ void k_deg(const int* __restrict__ ei) {
    int i = blockIdx.x * blockDim.x + threadIdx.x;
    if (i < NE) atomicAdd(&g_deg[ei[NE + i]], 1);
}

// K2: dis = rsqrt(deg + 1)  (+1 = self loop; always > 0)
__global__ void k_dis() {
    int i = blockIdx.x * blockDim.x + threadIdx.x;
    if (i < NN) g_dis[i] = rsqrtf((float)(g_deg[i] + 1));
}

// ---------------------------------------------------------------------------
// K3: y = (x @ W_enc) * dis[row].  16 rows/block, 128 threads (thread = out col)
__global__ __launch_bounds__(128) void k_gemm1(const float* __restrict__ x,
                                               const float* __restrict__ W) {
    __shared__ float xs[16 * IC];  // 32 KB
    const int tid = threadIdx.x;
    const int m0 = blockIdx.x * 16;

    // load 16 full input rows (2048 float4)
    const float4* x4 = (const float4*)(x + (size_t)m0 * IC);
    float4* xs4 = (float4*)xs;
#pragma unroll
    for (int t = 0; t < 16; t++)
        xs4[t * 128 + tid] = x4[t * 128 + tid];
    __syncthreads();

    float acc[16];
#pragma unroll
    for (int m = 0; m < 16; m++) acc[m] = 0.f;

    for (int k = 0; k < IC; k += 4) {
        float w0 = W[(k + 0) * OC + tid];
        float w1 = W[(k + 1) * OC + tid];
        float w2 = W[(k + 2) * OC + tid];
        float w3 = W[(k + 3) * OC + tid];
#pragma unroll
        for (int m = 0; m < 16; m++) {
            float4 xv = *(const float4*)&xs[m * IC + k];
            acc[m] = fmaf(xv.x, w0, acc[m]);
            acc[m] = fmaf(xv.y, w1, acc[m]);
            acc[m] = fmaf(xv.z, w2, acc[m]);
            acc[m] = fmaf(xv.w, w3, acc[m]);
        }
    }
#pragma unroll
    for (int m = 0; m < 16; m++) {
        int n = m0 + m;
        g_y[(size_t)n * OC + tid] = acc[m] * g_dis[n];
    }
}

// ---------------------------------------------------------------------------
// K4: edge scatter-add: agg[dst] += y[src].  One warp per edge, float4 lanes,
// vector reduction atomics (red.global.add.v4.f32, sm_90+).
__global__ __launch_bounds__(256) void k_edges(const int* __restrict__ ei) {
    long long gt = (long long)blockIdx.x * blockDim.x + threadIdx.x;
    int e = (int)(gt >> 5);
    if (e >= NE) return;
    int lane = threadIdx.x & 31;
    int s = ei[e];
    int d = ei[NE + e];
    float4 v = ((const float4*)g_y)[(size_t)s * 32 + lane];
    float* a = g_agg + (size_t)d * OC + lane * 4;
    asm volatile("red.global.add.v4.f32 [%0], {%1,%2,%3,%4};"
                 :: "l"(a), "f"(v.x), "f"(v.y), "f"(v.z), "f"(v.w)
                 : "memory");
}

// ---------------------------------------------------------------------------
// K5: fused epilogue + decode GEMM + softmax.
// 16 nodes/block, 128 threads; thread j owns output cols [4j, 4j+3].
__global__ __launch_bounds__(128) void k_dec(const float* __restrict__ b,
                                             const float* __restrict__ Wd,
                                             float* __restrict__ out) {
    __shared__ float hs[16 * OC];  // 8 KB
    __shared__ float red[4];
    const int tid = threadIdx.x;
    const int lane = tid & 31;
    const int warp = tid >> 5;
    const int n0 = blockIdx.x * 16;

    // h = relu(dis*(agg + y) + b)
    float bj = b[tid];
#pragma unroll
    for (int m = 0; m < 16; m++) {
        int n = n0 + m;
        size_t off = (size_t)n * OC + tid;
        float v = g_dis[n] * (g_agg[off] + g_y[off]) + bj;
        hs[m * OC + tid] = fmaxf(v, 0.f);
    }
    __syncthreads();

    // logits tile: acc[m] = h[m] @ Wd[:, 4*tid .. 4*tid+3]
    float4 acc[16];
#pragma unroll
    for (int m = 0; m < 16; m++) acc[m] = make_float4(0.f, 0.f, 0.f, 0.f);

    const float4* W4 = (const float4*)Wd;  // row k = 128 float4
    for (int k = 0; k < OC; k += 4) {
        float4 w0 = W4[(k + 0) * 128 + tid];
        float4 w1 = W4[(k + 1) * 128 + tid];
        float4 w2 = W4[(k + 2) * 128 + tid];
        float4 w3 = W4[(k + 3) * 128 + tid];
#pragma unroll
        for (int m = 0; m < 16; m++) {
            float4 hv = *(const float4*)&hs[m * OC + k];
            acc[m].x = fmaf(hv.x, w0.x, acc[m].x);
            acc[m].y = fmaf(hv.x, w0.y, acc[m].y);
            acc[m].z = fmaf(hv.x, w0.z, acc[m].z);
            acc[m].w = fmaf(hv.x, w0.w, acc[m].w);
            acc[m].x = fmaf(hv.y, w1.x, acc[m].x);
            acc[m].y = fmaf(hv.y, w1.y, acc[m].y);
            acc[m].z = fmaf(hv.y, w1.z, acc[m].z);
            acc[m].w = fmaf(hv.y, w1.w, acc[m].w);
            acc[m].x = fmaf(hv.z, w2.x, acc[m].x);
            acc[m].y = fmaf(hv.z, w2.y, acc[m].y);
            acc[m].z = fmaf(hv.z, w2.z, acc[m].z);
            acc[m].w = fmaf(hv.z, w2.w, acc[m].w);
            acc[m].x = fmaf(hv.w, w3.x, acc[m].x);
            acc[m].y = fmaf(hv.w, w3.y, acc[m].y);
            acc[m].z = fmaf(hv.w, w3.z, acc[m].z);
            acc[m].w = fmaf(hv.w, w3.w, acc[m].w);
        }
    }

    // per-node softmax over 512 logits spread across the block
#pragma unroll 1
    for (int m = 0; m < 16; m++) {
        float4 a4 = acc[m];
        float lm = fmaxf(fmaxf(a4.x, a4.y), fmaxf(a4.z, a4.w));
#pragma unroll
        for (int o = 16; o; o >>= 1)
            lm = fmaxf(lm, __shfl_xor_sync(0xffffffffu, lm, o));
        if (lane == 0) red[warp] = lm;
        __syncthreads();
        float rm = fmaxf(fmaxf(red[0], red[1]), fmaxf(red[2], red[3]));
        __syncthreads();

        float e0 = __expf(a4.x - rm);
        float e1 = __expf(a4.y - rm);
        float e2 = __expf(a4.z - rm);
        float e3 = __expf(a4.w - rm);
        float ls = (e0 + e1) + (e2 + e3);
#pragma unroll
        for (int o = 16; o; o >>= 1)
            ls += __shfl_xor_sync(0xffffffffu, ls, o);
        if (lane == 0) red[warp] = ls;
        __syncthreads();
        float inv = 1.f / (red[0] + red[1] + red[2] + red[3]);
        __syncthreads();

        int n = n0 + m;
        ((float4*)out)[(size_t)n * 128 + tid] =
            make_float4(e0 * inv, e1 * inv, e2 * inv, e3 * inv);
    }
}

// ---------------------------------------------------------------------------
extern "C" void kernel_launch(void* const* d_in, const int* in_sizes, int n_in,
                              void* d_out, int out_size) {
    const float* x    = (const float*)d_in[0];
    const int*   ei   = (const int*)d_in[1];   // int64 in reference, int32 in harness
    const float* Wenc = (const float*)d_in[2];
    const float* benc = (const float*)d_in[3];
    const float* Wdec = (const float*)d_in[4];
    float*       out  = (float*)d_out;

    k_zero<<<2048, 256>>>();
    k_deg<<<(NE + 255) / 256, 256>>>(ei);
    k_dis<<<(NN + 255) / 256, 256>>>();
    k_gemm1<<<NN / 16, 128>>>(x, Wenc);
    {
        long long threads = (long long)NE * 32;
        int blocks = (int)((threads + 255) / 256);
        k_edges<<<blocks, 256>>>(ei);
    }
    k_dec<<<NN / 16, 128>>>(benc, Wdec, out);
}